// round 2
// baseline (speedup 1.0000x reference)
#include <cuda_runtime.h>
#include <math.h>

#define NE 200000
#define NU 100000
#define NEDGE 1000000
#define HDIM 128

// ---------------- scratch (static device arrays; no allocation) ----------------
__device__ float g_xe[(size_t)NE * HDIM];     // xe, later reused for e2
__device__ float g_accE[(size_t)NE * HDIM];   // accum for email dst (conv1 + conv3)
__device__ float g_e1[(size_t)NE * HDIM];
__device__ float g_accU[(size_t)NU * HDIM];
__device__ float g_u1[(size_t)NU * HDIM];
__device__ float g_h[(size_t)NE * 64];
__device__ float g_cntE[NE];
__device__ float g_cntU[NU];

// ---------------- zero kernel (graph-capture-safe) ----------------
__global__ void zero_kernel(float4* __restrict__ p, int n4) {
    int i = blockIdx.x * blockDim.x + threadIdx.x;
    int stride = gridDim.x * blockDim.x;
    float4 z = make_float4(0.f, 0.f, 0.f, 0.f);
    for (; i < n4; i += stride) p[i] = z;
}

// ---------------- edge scatter: one warp per edge ----------------
__global__ void scatter_kernel(const int* __restrict__ src, const int* __restrict__ dst,
                               const float* __restrict__ xsrc,
                               float* __restrict__ accum, float* __restrict__ cnt,
                               int nE, int doCnt)
{
    int gt = blockIdx.x * blockDim.x + threadIdx.x;
    int e = gt >> 5, lane = gt & 31;
    if (e >= nE) return;
    int s = __ldg(src + e);
    int d = __ldg(dst + e);
    float4 v = *reinterpret_cast<const float4*>(xsrc + (size_t)s * HDIM + lane * 4);
    float* a = accum + (size_t)d * HDIM + lane * 4;
    atomicAdd(a + 0, v.x);
    atomicAdd(a + 1, v.y);
    atomicAdd(a + 2, v.z);
    atomicAdd(a + 3, v.w);
    if (doCnt && lane == 0) atomicAdd(cnt + d, 1.0f);
}

// ---------------- fused combine GEMM ----------------
// out[M,128] = epi( A1[M,K1] (optionally * 1/max(cnt,1) per row) @ W1[128,K1]^T
//                   + (HAS_A2 ? A2[M,128] @ W2[128,128]^T : 0) + bias )
// BM=128, BN=128, BK=32, 256 threads, TM=TN=8.
template<bool HAS_A2, bool RELU, bool MEAN>
__global__ void gemm_combine(const float* __restrict__ A1, int K1,
                             const float* __restrict__ W1,
                             const float* __restrict__ A2,
                             const float* __restrict__ W2,
                             const float* __restrict__ bias,
                             const float* __restrict__ cnt,
                             float* __restrict__ out, int M)
{
    __shared__ float As[32][132];
    __shared__ float Ws[32][132];
    int tid = threadIdx.x;
    int ty = tid >> 4, tx = tid & 15;
    int row0 = blockIdx.x * 128;
    float acc[8][8];
#pragma unroll
    for (int i = 0; i < 8; i++)
#pragma unroll
        for (int j = 0; j < 8; j++) acc[i][j] = 0.f;

    const int nsrc = HAS_A2 ? 2 : 1;
    for (int sphase = 0; sphase < nsrc; sphase++) {
        const float* A = (sphase == 0) ? A1 : A2;
        const float* W = (sphase == 0) ? W1 : W2;
        int K = (sphase == 0) ? K1 : 128;
        for (int k0 = 0; k0 < K; k0 += 32) {
#pragma unroll
            for (int it = 0; it < 16; it++) {
                int idx = tid + it * 256;
                int kk = idx & 31, r = idx >> 5;
                int gr = row0 + r;
                float v = 0.f;
                if (gr < M) v = A[(size_t)gr * K + k0 + kk];
                As[kk][r] = v;
            }
#pragma unroll
            for (int it = 0; it < 16; it++) {
                int idx = tid + it * 256;
                int kk = idx & 31, c = idx >> 5;
                Ws[kk][c] = W[(size_t)c * K + k0 + kk];
            }
            __syncthreads();
#pragma unroll
            for (int kk = 0; kk < 32; kk++) {
                float a[8], w[8];
#pragma unroll
                for (int i = 0; i < 8; i++) a[i] = As[kk][ty * 8 + i];
#pragma unroll
                for (int j = 0; j < 8; j++) w[j] = Ws[kk][tx * 8 + j];
#pragma unroll
                for (int i = 0; i < 8; i++)
#pragma unroll
                    for (int j = 0; j < 8; j++) acc[i][j] += a[i] * w[j];
            }
            __syncthreads();
        }
        // after source-0: apply mean scaling (diag(1/cnt) commutes with GEMM)
        if (MEAN && sphase == 0) {
#pragma unroll
            for (int i = 0; i < 8; i++) {
                int gr = row0 + ty * 8 + i;
                float c = (gr < M) ? cnt[gr] : 1.f;
                float inv = 1.f / fmaxf(c, 1.f);
#pragma unroll
                for (int j = 0; j < 8; j++) acc[i][j] *= inv;
            }
        }
    }
#pragma unroll
    for (int i = 0; i < 8; i++) {
        int gr = row0 + ty * 8 + i;
        if (gr < M) {
#pragma unroll
            for (int j = 0; j < 8; j++) {
                int c = tx * 8 + j;
                float v = acc[i][j] + bias[c];
                if (RELU) v = fmaxf(v, 0.f);
                out[(size_t)gr * 128 + c] = v;
            }
        }
    }
}

// ---------------- B-spline bases (uniform grid, grid_size=5, k=3 -> 8 bases) ----
__device__ __forceinline__ void bspline8(float x, float b[8]) {
    const float hstep = 2.0f / 5.0f;
    float g[12];
#pragma unroll
    for (int t = 0; t < 12; t++) g[t] = (float)(t - 3) * hstep - 1.0f;
    float p0[11], p1[10], p2[9];
#pragma unroll
    for (int t = 0; t < 11; t++) p0[t] = (x >= g[t] && x < g[t + 1]) ? 1.0f : 0.0f;
#pragma unroll
    for (int t = 0; t < 10; t++)
        p1[t] = (x - g[t]) * (1.0f / (g[t + 1] - g[t])) * p0[t]
              + (g[t + 2] - x) * (1.0f / (g[t + 2] - g[t + 1])) * p0[t + 1];
#pragma unroll
    for (int t = 0; t < 9; t++)
        p2[t] = (x - g[t]) * (1.0f / (g[t + 2] - g[t])) * p1[t]
              + (g[t + 3] - x) * (1.0f / (g[t + 3] - g[t + 1])) * p1[t + 1];
#pragma unroll
    for (int t = 0; t < 8; t++)
        b[t] = (x - g[t]) * (1.0f / (g[t + 3] - g[t])) * p2[t]
             + (g[t + 4] - x) * (1.0f / (g[t + 4] - g[t + 1])) * p2[t + 1];
}

__device__ __forceinline__ float silu(float x) {
    return x / (1.0f + __expf(-x));
}

// ---------------- KAN layer 1: [M,128] -> [M,64] fully fused ----------------
// BM=128 rows, all 64 cols, 256 threads (ty 0..15: TM=8 rows; tx 0..15: TN=4 cols)
__global__ void kan1_kernel(const float* __restrict__ x,      // [M,128]
                            const float* __restrict__ spline,  // [64,128,8]
                            const float* __restrict__ scaler,  // [64,128]
                            const float* __restrict__ basew,   // [64,128]
                            float* __restrict__ out, int M)    // [M,64]
{
    __shared__ float Bs[32][129];
    __shared__ float Ws[32][65];
    int tid = threadIdx.x;
    int ty = tid >> 4, tx = tid & 15;
    int row0 = blockIdx.x * 128;
    float acc[8][4];
#pragma unroll
    for (int i = 0; i < 8; i++)
#pragma unroll
        for (int j = 0; j < 4; j++) acc[i][j] = 0.f;

    // spline part: 32 chunks of 4 input features (= 32 basis K-values each)
    for (int f0 = 0; f0 < 128; f0 += 4) {
#pragma unroll
        for (int it = 0; it < 2; it++) {
            int p = tid + it * 256;
            int feat = p & 3, r = p >> 2;
            int gr = row0 + r;
            float xv = (gr < M) ? x[(size_t)gr * 128 + f0 + feat] : 0.f;
            float b[8];
            bspline8(xv, b);
#pragma unroll
            for (int t = 0; t < 8; t++) Bs[feat * 8 + t][r] = b[t];
        }
#pragma unroll
        for (int it = 0; it < 8; it++) {
            int idx = tid + it * 256;
            int kk = idx & 31, c = idx >> 5;
            float w = spline[(size_t)c * 1024 + f0 * 8 + kk] * scaler[c * 128 + f0 + (kk >> 3)];
            Ws[kk][c] = w;
        }
        __syncthreads();
#pragma unroll
        for (int kk = 0; kk < 32; kk++) {
            float a[8], w[4];
#pragma unroll
            for (int i = 0; i < 8; i++) a[i] = Bs[kk][ty * 8 + i];
#pragma unroll
            for (int j = 0; j < 4; j++) w[j] = Ws[kk][tx * 4 + j];
#pragma unroll
            for (int i = 0; i < 8; i++)
#pragma unroll
                for (int j = 0; j < 4; j++) acc[i][j] += a[i] * w[j];
        }
        __syncthreads();
    }

    // base part: silu(x) @ base_w^T, 4 chunks of 32 features
    for (int f0 = 0; f0 < 128; f0 += 32) {
#pragma unroll
        for (int it = 0; it < 16; it++) {
            int p = tid + it * 256;
            int feat = p & 31, r = p >> 5;
            int gr = row0 + r;
            float xv = (gr < M) ? x[(size_t)gr * 128 + f0 + feat] : 0.f;
            Bs[feat][r] = silu(xv);
        }
#pragma unroll
        for (int it = 0; it < 8; it++) {
            int idx = tid + it * 256;
            int kk = idx & 31, c = idx >> 5;
            Ws[kk][c] = basew[(size_t)c * 128 + f0 + kk];
        }
        __syncthreads();
#pragma unroll
        for (int kk = 0; kk < 32; kk++) {
            float a[8], w[4];
#pragma unroll
            for (int i = 0; i < 8; i++) a[i] = Bs[kk][ty * 8 + i];
#pragma unroll
            for (int j = 0; j < 4; j++) w[j] = Ws[kk][tx * 4 + j];
#pragma unroll
            for (int i = 0; i < 8; i++)
#pragma unroll
                for (int j = 0; j < 4; j++) acc[i][j] += a[i] * w[j];
        }
        __syncthreads();
    }

#pragma unroll
    for (int i = 0; i < 8; i++) {
        int gr = row0 + ty * 8 + i;
        if (gr < M) {
#pragma unroll
            for (int j = 0; j < 4; j++) out[(size_t)gr * 64 + tx * 4 + j] = acc[i][j];
        }
    }
}

// ---------------- KAN layer 2: [M,64] -> [M,2], one thread per row ----------------
__global__ void kan2_kernel(const float* __restrict__ hin,     // [M,64]
                            const float* __restrict__ spline,  // [2,64,8]
                            const float* __restrict__ scaler,  // [2,64]
                            const float* __restrict__ basew,   // [2,64]
                            float* __restrict__ out, int M)    // [M,2]
{
    __shared__ float sh[128][65];
    __shared__ float sw[2][64][8];
    __shared__ float sb[2][64];
    int tid = threadIdx.x;
    int row0 = blockIdx.x * 128;
    for (int idx = tid; idx < 1024; idx += 128) {
        int o = idx >> 9, rem = idx & 511, f = rem >> 3, t = rem & 7;
        sw[o][f][t] = spline[idx] * scaler[o * 64 + f];
    }
    if (tid < 128) sb[tid >> 6][tid & 63] = basew[tid];
    for (int idx = tid; idx < 128 * 64; idx += 128) {
        int r = idx >> 6, f = idx & 63;
        int gr = row0 + r;
        sh[r][f] = (gr < M) ? hin[(size_t)gr * 64 + f] : 0.f;
    }
    __syncthreads();
    int gr = row0 + tid;
    if (gr >= M) return;
    float acc0 = 0.f, acc1 = 0.f;
    for (int f = 0; f < 64; f++) {
        float xv = sh[tid][f];
        float s = silu(xv);
        acc0 += s * sb[0][f];
        acc1 += s * sb[1][f];
        float b[8];
        bspline8(xv, b);
#pragma unroll
        for (int t = 0; t < 8; t++) {
            acc0 += b[t] * sw[0][f][t];
            acc1 += b[t] * sw[1][f][t];
        }
    }
    out[(size_t)gr * 2 + 0] = acc0;
    out[(size_t)gr * 2 + 1] = acc1;
}

// ---------------- launch ----------------
extern "C" void kernel_launch(void* const* d_in, const int* in_sizes, int n_in,
                              void* d_out, int out_size)
{
    const float* x_email    = (const float*)d_in[0];
    const int*   ei_ue      = (const int*)d_in[1];   // [2,E]: row0=src(user), row1=dst(email)
    const int*   ei_eu      = (const int*)d_in[2];   // [2,E]: row0=src(email), row1=dst(user)
    const float* w_email    = (const float*)d_in[3];
    const float* b_email    = (const float*)d_in[4];
    const float* emb_user   = (const float*)d_in[5];
    const float* w_l1_ue_n  = (const float*)d_in[6];
    const float* b_l1_ue    = (const float*)d_in[7];
    const float* w_l1_ue_r  = (const float*)d_in[8];
    const float* w_l1_eu_n  = (const float*)d_in[9];
    const float* b_l1_eu    = (const float*)d_in[10];
    const float* w_l1_eu_r  = (const float*)d_in[11];
    const float* w_l2_ue_n  = (const float*)d_in[12];
    const float* b_l2_ue    = (const float*)d_in[13];
    const float* w_l2_ue_r  = (const float*)d_in[14];
    // 15..17: l2_eu weights (unused by the reference output path)
    const float* kan1_base   = (const float*)d_in[18];
    const float* kan1_spline = (const float*)d_in[19];
    const float* kan1_scaler = (const float*)d_in[20];
    // 21: grid1 (uniform; recomputed in-kernel)
    const float* kan2_base   = (const float*)d_in[22];
    const float* kan2_spline = (const float*)d_in[23];
    const float* kan2_scaler = (const float*)d_in[24];
    // 25: grid2
    float* out = (float*)d_out;

    float *xe, *accE, *e1, *accU, *u1, *hbuf, *cntE, *cntU;
    cudaGetSymbolAddress((void**)&xe,   g_xe);
    cudaGetSymbolAddress((void**)&accE, g_accE);
    cudaGetSymbolAddress((void**)&e1,   g_e1);
    cudaGetSymbolAddress((void**)&accU, g_accU);
    cudaGetSymbolAddress((void**)&u1,   g_u1);
    cudaGetSymbolAddress((void**)&hbuf, g_h);
    cudaGetSymbolAddress((void**)&cntE, g_cntE);
    cudaGetSymbolAddress((void**)&cntU, g_cntU);

    const int ZB = 256;
    // zero accumulators + counts
    zero_kernel<<<4096, ZB>>>((float4*)accE, NE * HDIM / 4);
    zero_kernel<<<2048, ZB>>>((float4*)accU, NU * HDIM / 4);
    zero_kernel<<<256,  ZB>>>((float4*)cntE, NE / 4);
    zero_kernel<<<128,  ZB>>>((float4*)cntU, NU / 4);

    int gE = (NE + 127) / 128;   // 1563
    int gU = (NU + 127) / 128;   // 782
    int gScat = (NEDGE * 32 + 255) / 256;  // 125000

    // xe = x_email @ w_email^T + b_email
    gemm_combine<false, false, false><<<gE, 256>>>(x_email, 64, w_email,
                                                   nullptr, nullptr, b_email,
                                                   nullptr, xe, NE);
    // conv1 email: aggregate users -> emails
    scatter_kernel<<<gScat, 256>>>(ei_ue, ei_ue + NEDGE, emb_user, accE, cntE, NEDGE, 1);
    gemm_combine<true, true, true><<<gE, 256>>>(accE, 128, w_l1_ue_n,
                                                xe, w_l1_ue_r, b_l1_ue,
                                                cntE, e1, NE);
    // conv1 user: aggregate emails -> users
    scatter_kernel<<<gScat, 256>>>(ei_eu, ei_eu + NEDGE, xe, accU, cntU, NEDGE, 1);
    gemm_combine<true, true, true><<<gU, 256>>>(accU, 128, w_l1_eu_n,
                                                emb_user, w_l1_eu_r, b_l1_eu,
                                                cntU, u1, NU);
    // conv2 email: aggregate u1 -> emails (same edge list/counts as conv1 email)
    zero_kernel<<<4096, ZB>>>((float4*)accE, NE * HDIM / 4);
    scatter_kernel<<<gScat, 256>>>(ei_ue, ei_ue + NEDGE, u1, accE, nullptr, NEDGE, 0);
    gemm_combine<true, true, true><<<gE, 256>>>(accE, 128, w_l2_ue_n,
                                                e1, w_l2_ue_r, b_l2_ue,
                                                cntE, xe /*= e2*/, NE);
    // KAN head
    kan1_kernel<<<gE, 256>>>(xe, kan1_spline, kan1_scaler, kan1_base, hbuf, NE);
    kan2_kernel<<<gE, 128>>>(hbuf, kan2_spline, kan2_scaler, kan2_base, out, NE);
}

// round 3
// speedup vs baseline: 1.2858x; 1.2858x over previous
#include <cuda_runtime.h>
#include <math.h>

#define NE 200000
#define NU 100000
#define NEDGE 1000000
#define HDIM 128

// ---------------- scratch (static device arrays; no allocation) ----------------
__device__ float g_xe[(size_t)NE * HDIM];     // xe, later reused for e2
__device__ float g_accE[(size_t)NE * HDIM];   // accum for email dst (conv1 + conv3)
__device__ float g_e1[(size_t)NE * HDIM];
__device__ float g_accU[(size_t)NU * HDIM];
__device__ float g_u1[(size_t)NU * HDIM];
__device__ float g_h[(size_t)NE * 64];
__device__ float g_cntE[NE];
__device__ float g_cntU[NU];

// ---------------- f32x2 packed helpers ----------------
__device__ __forceinline__ void fma_x2(unsigned long long& acc, unsigned long long a,
                                       unsigned long long b) {
    asm("fma.rn.f32x2 %0, %1, %2, %0;" : "+l"(acc) : "l"(a), "l"(b));
}
__device__ __forceinline__ void mul_x2(unsigned long long& acc, unsigned long long s) {
    asm("mul.rn.f32x2 %0, %0, %1;" : "+l"(acc) : "l"(s));
}
__device__ __forceinline__ unsigned long long dup_x2(float v) {
    unsigned long long r;
    asm("mov.b64 %0, {%1, %1};" : "=l"(r) : "f"(v));
    return r;
}
__device__ __forceinline__ unsigned long long pack_x2(float lo, float hi) {
    unsigned long long r;
    asm("mov.b64 %0, {%1, %2};" : "=l"(r) : "f"(lo), "f"(hi));
    return r;
}
__device__ __forceinline__ void unpack_x2(unsigned long long v, float& lo, float& hi) {
    asm("mov.b64 {%0, %1}, %2;" : "=f"(lo), "=f"(hi) : "l"(v));
}

// ---------------- zero kernel (graph-capture-safe) ----------------
__global__ void zero_kernel(float4* __restrict__ p, int n4) {
    int i = blockIdx.x * blockDim.x + threadIdx.x;
    int stride = gridDim.x * blockDim.x;
    float4 z = make_float4(0.f, 0.f, 0.f, 0.f);
    for (; i < n4; i += stride) p[i] = z;
}

// ---------------- edge scatter: one warp per edge, vector RED ----------------
__global__ void scatter_kernel(const int* __restrict__ src, const int* __restrict__ dst,
                               const float* __restrict__ xsrc,
                               float* __restrict__ accum, float* __restrict__ cnt,
                               int nE, int doCnt)
{
    int gt = blockIdx.x * blockDim.x + threadIdx.x;
    int e = gt >> 5, lane = gt & 31;
    if (e >= nE) return;
    int s = __ldg(src + e);
    int d = __ldg(dst + e);
    float4 v = *reinterpret_cast<const float4*>(xsrc + (size_t)s * HDIM + lane * 4);
    float* a = accum + (size_t)d * HDIM + lane * 4;
    asm volatile("red.global.add.v4.f32 [%0], {%1, %2, %3, %4};"
                 :: "l"(a), "f"(v.x), "f"(v.y), "f"(v.z), "f"(v.w) : "memory");
    if (doCnt && lane == 0) atomicAdd(cnt + d, 1.0f);
}

// ---------------- fused combine GEMM (f32x2 packed math) ----------------
// out[M,128] = epi( A1[M,K1] (optionally * 1/max(cnt,1) per row) @ W1[128,K1]^T
//                   + (HAS_A2 ? A2[M,128] @ W2[128,128]^T : 0) + bias )
// BM=128, BN=128, BK=32, 256 threads; each thread: 8 rows (4 packed pairs) x 8 cols.
template<bool HAS_A2, bool RELU, bool MEAN>
__global__ void gemm_combine(const float* __restrict__ A1, int K1,
                             const float* __restrict__ W1,
                             const float* __restrict__ A2,
                             const float* __restrict__ W2,
                             const float* __restrict__ bias,
                             const float* __restrict__ cnt,
                             float* __restrict__ out, int M)
{
    __shared__ float As[32][132];
    __shared__ float Ws[32][132];
    int tid = threadIdx.x;
    int ty = tid >> 4, tx = tid & 15;
    int row0 = blockIdx.x * 128;
    unsigned long long acc[4][8];   // [row-pair][col] packed (row 2p, row 2p+1)
#pragma unroll
    for (int p = 0; p < 4; p++)
#pragma unroll
        for (int j = 0; j < 8; j++) acc[p][j] = 0ULL;

    const int nsrc = HAS_A2 ? 2 : 1;
    for (int sphase = 0; sphase < nsrc; sphase++) {
        const float* A = (sphase == 0) ? A1 : A2;
        const float* W = (sphase == 0) ? W1 : W2;
        int K = (sphase == 0) ? K1 : 128;
        for (int k0 = 0; k0 < K; k0 += 32) {
#pragma unroll
            for (int it = 0; it < 16; it++) {
                int idx = tid + it * 256;
                int kk = idx & 31, r = idx >> 5;
                int gr = row0 + r;
                float v = 0.f;
                if (gr < M) v = A[(size_t)gr * K + k0 + kk];
                As[kk][r] = v;
            }
#pragma unroll
            for (int it = 0; it < 16; it++) {
                int idx = tid + it * 256;
                int kk = idx & 31, c = idx >> 5;
                Ws[kk][c] = W[(size_t)c * K + k0 + kk];
            }
            __syncthreads();
#pragma unroll
            for (int kk = 0; kk < 32; kk++) {
                unsigned long long a2[4];
#pragma unroll
                for (int p = 0; p < 4; p++)
                    a2[p] = *reinterpret_cast<const unsigned long long*>(&As[kk][ty * 8 + 2 * p]);
                unsigned long long wd[8];
#pragma unroll
                for (int j = 0; j < 8; j++) wd[j] = dup_x2(Ws[kk][tx * 8 + j]);
#pragma unroll
                for (int p = 0; p < 4; p++)
#pragma unroll
                    for (int j = 0; j < 8; j++) fma_x2(acc[p][j], a2[p], wd[j]);
            }
            __syncthreads();
        }
        // after source-0: apply mean scaling (diag(1/cnt) commutes with GEMM)
        if (MEAN && sphase == 0) {
#pragma unroll
            for (int p = 0; p < 4; p++) {
                int gr0 = row0 + ty * 8 + 2 * p;
                int gr1 = gr0 + 1;
                float c0 = (gr0 < M) ? cnt[gr0] : 1.f;
                float c1 = (gr1 < M) ? cnt[gr1] : 1.f;
                unsigned long long invp = pack_x2(1.f / fmaxf(c0, 1.f), 1.f / fmaxf(c1, 1.f));
#pragma unroll
                for (int j = 0; j < 8; j++) mul_x2(acc[p][j], invp);
            }
        }
    }

    float bj[8];
#pragma unroll
    for (int j = 0; j < 8; j++) bj[j] = bias[tx * 8 + j];

#pragma unroll
    for (int p = 0; p < 4; p++) {
        int gr0 = row0 + ty * 8 + 2 * p;
        int gr1 = gr0 + 1;
        float r0[8], r1[8];
#pragma unroll
        for (int j = 0; j < 8; j++) {
            unpack_x2(acc[p][j], r0[j], r1[j]);
            r0[j] += bj[j]; r1[j] += bj[j];
            if (RELU) { r0[j] = fmaxf(r0[j], 0.f); r1[j] = fmaxf(r1[j], 0.f); }
        }
        if (gr0 < M) {
            float4* o = reinterpret_cast<float4*>(out + (size_t)gr0 * 128 + tx * 8);
            o[0] = make_float4(r0[0], r0[1], r0[2], r0[3]);
            o[1] = make_float4(r0[4], r0[5], r0[6], r0[7]);
        }
        if (gr1 < M) {
            float4* o = reinterpret_cast<float4*>(out + (size_t)gr1 * 128 + tx * 8);
            o[0] = make_float4(r1[0], r1[1], r1[2], r1[3]);
            o[1] = make_float4(r1[4], r1[5], r1[6], r1[7]);
        }
    }
}

// ---------------- B-spline bases (uniform grid, grid_size=5, k=3 -> 8 bases) ----
__device__ __forceinline__ void bspline8(float x, float b[8]) {
    const float hstep = 2.0f / 5.0f;
    float g[12];
#pragma unroll
    for (int t = 0; t < 12; t++) g[t] = (float)(t - 3) * hstep - 1.0f;
    float p0[11], p1[10], p2[9];
#pragma unroll
    for (int t = 0; t < 11; t++) p0[t] = (x >= g[t] && x < g[t + 1]) ? 1.0f : 0.0f;
#pragma unroll
    for (int t = 0; t < 10; t++)
        p1[t] = (x - g[t]) * (1.0f / (g[t + 1] - g[t])) * p0[t]
              + (g[t + 2] - x) * (1.0f / (g[t + 2] - g[t + 1])) * p0[t + 1];
#pragma unroll
    for (int t = 0; t < 9; t++)
        p2[t] = (x - g[t]) * (1.0f / (g[t + 2] - g[t])) * p1[t]
              + (g[t + 3] - x) * (1.0f / (g[t + 3] - g[t + 1])) * p1[t + 1];
#pragma unroll
    for (int t = 0; t < 8; t++)
        b[t] = (x - g[t]) * (1.0f / (g[t + 3] - g[t])) * p2[t]
             + (g[t + 4] - x) * (1.0f / (g[t + 4] - g[t + 1])) * p2[t + 1];
}

__device__ __forceinline__ float silu(float x) {
    return x / (1.0f + __expf(-x));
}

// ---------------- KAN layer 1: [M,128] -> [M,64] fully fused, f32x2 math --------
// BM=128 rows, all 64 cols, 256 threads (ty: 8 rows = 4 packed pairs; tx: 4 cols)
__global__ void kan1_kernel(const float* __restrict__ x,      // [M,128]
                            const float* __restrict__ spline,  // [64,128,8]
                            const float* __restrict__ scaler,  // [64,128]
                            const float* __restrict__ basew,   // [64,128]
                            float* __restrict__ out, int M)    // [M,64]
{
    __shared__ float Bs[32][130];   // even stride -> 8B-aligned 64-bit LDS
    __shared__ float Ws[32][65];
    int tid = threadIdx.x;
    int ty = tid >> 4, tx = tid & 15;
    int row0 = blockIdx.x * 128;
    unsigned long long acc[4][4];
#pragma unroll
    for (int p = 0; p < 4; p++)
#pragma unroll
        for (int j = 0; j < 4; j++) acc[p][j] = 0ULL;

    // spline part: 32 chunks of 4 input features (= 32 basis K-values each)
    for (int f0 = 0; f0 < 128; f0 += 4) {
#pragma unroll
        for (int it = 0; it < 2; it++) {
            int p = tid + it * 256;
            int feat = p & 3, r = p >> 2;
            int gr = row0 + r;
            float xv = (gr < M) ? x[(size_t)gr * 128 + f0 + feat] : 0.f;
            float b[8];
            bspline8(xv, b);
#pragma unroll
            for (int t = 0; t < 8; t++) Bs[feat * 8 + t][r] = b[t];
        }
#pragma unroll
        for (int it = 0; it < 8; it++) {
            int idx = tid + it * 256;
            int kk = idx & 31, c = idx >> 5;
            float w = spline[(size_t)c * 1024 + f0 * 8 + kk] * scaler[c * 128 + f0 + (kk >> 3)];
            Ws[kk][c] = w;
        }
        __syncthreads();
#pragma unroll
        for (int kk = 0; kk < 32; kk++) {
            unsigned long long a2[4];
#pragma unroll
            for (int p = 0; p < 4; p++)
                a2[p] = *reinterpret_cast<const unsigned long long*>(&Bs[kk][ty * 8 + 2 * p]);
            unsigned long long wd[4];
#pragma unroll
            for (int j = 0; j < 4; j++) wd[j] = dup_x2(Ws[kk][tx * 4 + j]);
#pragma unroll
            for (int p = 0; p < 4; p++)
#pragma unroll
                for (int j = 0; j < 4; j++) fma_x2(acc[p][j], a2[p], wd[j]);
        }
        __syncthreads();
    }

    // base part: silu(x) @ base_w^T, 4 chunks of 32 features
    for (int f0 = 0; f0 < 128; f0 += 32) {
#pragma unroll
        for (int it = 0; it < 16; it++) {
            int p = tid + it * 256;
            int feat = p & 31, r = p >> 5;
            int gr = row0 + r;
            float xv = (gr < M) ? x[(size_t)gr * 128 + f0 + feat] : 0.f;
            Bs[feat][r] = silu(xv);
        }
#pragma unroll
        for (int it = 0; it < 8; it++) {
            int idx = tid + it * 256;
            int kk = idx & 31, c = idx >> 5;
            Ws[kk][c] = basew[(size_t)c * 128 + f0 + kk];
        }
        __syncthreads();
#pragma unroll
        for (int kk = 0; kk < 32; kk++) {
            unsigned long long a2[4];
#pragma unroll
            for (int p = 0; p < 4; p++)
                a2[p] = *reinterpret_cast<const unsigned long long*>(&Bs[kk][ty * 8 + 2 * p]);
            unsigned long long wd[4];
#pragma unroll
            for (int j = 0; j < 4; j++) wd[j] = dup_x2(Ws[kk][tx * 4 + j]);
#pragma unroll
            for (int p = 0; p < 4; p++)
#pragma unroll
                for (int j = 0; j < 4; j++) fma_x2(acc[p][j], a2[p], wd[j]);
        }
        __syncthreads();
    }

#pragma unroll
    for (int p = 0; p < 4; p++) {
        int gr0 = row0 + ty * 8 + 2 * p;
        int gr1 = gr0 + 1;
        float r0[4], r1[4];
#pragma unroll
        for (int j = 0; j < 4; j++) unpack_x2(acc[p][j], r0[j], r1[j]);
        if (gr0 < M)
            *reinterpret_cast<float4*>(out + (size_t)gr0 * 64 + tx * 4) =
                make_float4(r0[0], r0[1], r0[2], r0[3]);
        if (gr1 < M)
            *reinterpret_cast<float4*>(out + (size_t)gr1 * 64 + tx * 4) =
                make_float4(r1[0], r1[1], r1[2], r1[3]);
    }
}

// ---------------- KAN layer 2: [M,64] -> [M,2], one thread per row ----------------
__global__ void kan2_kernel(const float* __restrict__ hin,     // [M,64]
                            const float* __restrict__ spline,  // [2,64,8]
                            const float* __restrict__ scaler,  // [2,64]
                            const float* __restrict__ basew,   // [2,64]
                            float* __restrict__ out, int M)    // [M,2]
{
    __shared__ float sh[128][65];
    __shared__ float sw[2][64][8];
    __shared__ float sb[2][64];
    int tid = threadIdx.x;
    int row0 = blockIdx.x * 128;
    for (int idx = tid; idx < 1024; idx += 128) {
        int o = idx >> 9, rem = idx & 511, f = rem >> 3, t = rem & 7;
        sw[o][f][t] = spline[idx] * scaler[o * 64 + f];
    }
    if (tid < 128) sb[tid >> 6][tid & 63] = basew[tid];
    for (int idx = tid; idx < 128 * 64; idx += 128) {
        int r = idx >> 6, f = idx & 63;
        int gr = row0 + r;
        sh[r][f] = (gr < M) ? hin[(size_t)gr * 64 + f] : 0.f;
    }
    __syncthreads();
    int gr = row0 + tid;
    if (gr >= M) return;
    float acc0 = 0.f, acc1 = 0.f;
    for (int f = 0; f < 64; f++) {
        float xv = sh[tid][f];
        float s = silu(xv);
        acc0 += s * sb[0][f];
        acc1 += s * sb[1][f];
        float b[8];
        bspline8(xv, b);
#pragma unroll
        for (int t = 0; t < 8; t++) {
            acc0 += b[t] * sw[0][f][t];
            acc1 += b[t] * sw[1][f][t];
        }
    }
    out[(size_t)gr * 2 + 0] = acc0;
    out[(size_t)gr * 2 + 1] = acc1;
}

// ---------------- launch ----------------
extern "C" void kernel_launch(void* const* d_in, const int* in_sizes, int n_in,
                              void* d_out, int out_size)
{
    const float* x_email    = (const float*)d_in[0];
    const int*   ei_ue      = (const int*)d_in[1];   // [2,E]: row0=src(user), row1=dst(email)
    const int*   ei_eu      = (const int*)d_in[2];   // [2,E]: row0=src(email), row1=dst(user)
    const float* w_email    = (const float*)d_in[3];
    const float* b_email    = (const float*)d_in[4];
    const float* emb_user   = (const float*)d_in[5];
    const float* w_l1_ue_n  = (const float*)d_in[6];
    const float* b_l1_ue    = (const float*)d_in[7];
    const float* w_l1_ue_r  = (const float*)d_in[8];
    const float* w_l1_eu_n  = (const float*)d_in[9];
    const float* b_l1_eu    = (const float*)d_in[10];
    const float* w_l1_eu_r  = (const float*)d_in[11];
    const float* w_l2_ue_n  = (const float*)d_in[12];
    const float* b_l2_ue    = (const float*)d_in[13];
    const float* w_l2_ue_r  = (const float*)d_in[14];
    // 15..17: l2_eu weights (unused by the reference output path)
    const float* kan1_base   = (const float*)d_in[18];
    const float* kan1_spline = (const float*)d_in[19];
    const float* kan1_scaler = (const float*)d_in[20];
    // 21: grid1 (uniform; recomputed in-kernel)
    const float* kan2_base   = (const float*)d_in[22];
    const float* kan2_spline = (const float*)d_in[23];
    const float* kan2_scaler = (const float*)d_in[24];
    // 25: grid2
    float* out = (float*)d_out;

    float *xe, *accE, *e1, *accU, *u1, *hbuf, *cntE, *cntU;
    cudaGetSymbolAddress((void**)&xe,   g_xe);
    cudaGetSymbolAddress((void**)&accE, g_accE);
    cudaGetSymbolAddress((void**)&e1,   g_e1);
    cudaGetSymbolAddress((void**)&accU, g_accU);
    cudaGetSymbolAddress((void**)&u1,   g_u1);
    cudaGetSymbolAddress((void**)&hbuf, g_h);
    cudaGetSymbolAddress((void**)&cntE, g_cntE);
    cudaGetSymbolAddress((void**)&cntU, g_cntU);

    const int ZB = 256;
    // zero accumulators + counts
    zero_kernel<<<4096, ZB>>>((float4*)accE, NE * HDIM / 4);
    zero_kernel<<<2048, ZB>>>((float4*)accU, NU * HDIM / 4);
    zero_kernel<<<256,  ZB>>>((float4*)cntE, NE / 4);
    zero_kernel<<<128,  ZB>>>((float4*)cntU, NU / 4);

    int gE = (NE + 127) / 128;   // 1563
    int gU = (NU + 127) / 128;   // 782
    int gScat = (NEDGE * 32 + 255) / 256;  // 125000

    // xe = x_email @ w_email^T + b_email
    gemm_combine<false, false, false><<<gE, 256>>>(x_email, 64, w_email,
                                                   nullptr, nullptr, b_email,
                                                   nullptr, xe, NE);
    // conv1 email: aggregate users -> emails
    scatter_kernel<<<gScat, 256>>>(ei_ue, ei_ue + NEDGE, emb_user, accE, cntE, NEDGE, 1);
    gemm_combine<true, true, true><<<gE, 256>>>(accE, 128, w_l1_ue_n,
                                                xe, w_l1_ue_r, b_l1_ue,
                                                cntE, e1, NE);
    // conv1 user: aggregate emails -> users
    scatter_kernel<<<gScat, 256>>>(ei_eu, ei_eu + NEDGE, xe, accU, cntU, NEDGE, 1);
    gemm_combine<true, true, true><<<gU, 256>>>(accU, 128, w_l1_eu_n,
                                                emb_user, w_l1_eu_r, b_l1_eu,
                                                cntU, u1, NU);
    // conv2 email: aggregate u1 -> emails (same edge list/counts as conv1 email)
    zero_kernel<<<4096, ZB>>>((float4*)accE, NE * HDIM / 4);
    scatter_kernel<<<gScat, 256>>>(ei_ue, ei_ue + NEDGE, u1, accE, nullptr, NEDGE, 0);
    gemm_combine<true, true, true><<<gE, 256>>>(accE, 128, w_l2_ue_n,
                                                e1, w_l2_ue_r, b_l2_ue,
                                                cntE, xe /*= e2*/, NE);
    // KAN head
    kan1_kernel<<<gE, 256>>>(xe, kan1_spline, kan1_scaler, kan1_base, hbuf, NE);
    kan2_kernel<<<gE, 128>>>(hbuf, kan2_spline, kan2_scaler, kan2_base, out, NE);
}

// round 4
// speedup vs baseline: 1.4799x; 1.1509x over previous
#include <cuda_runtime.h>
#include <math.h>

#define NE 200000
#define NU 100000
#define NEDGE 1000000
#define HDIM 128

// ---------------- scratch (static device arrays; no allocation) ----------------
__device__ float g_xe[(size_t)NE * HDIM];     // xe, later reused for e2
__device__ float g_accE[(size_t)NE * HDIM];   // accum for conv1-email
__device__ float g_accE2[(size_t)NE * HDIM];  // accum for conv2-email
__device__ float g_e1[(size_t)NE * HDIM];
__device__ float g_accU[(size_t)NU * HDIM];
__device__ float g_u1[(size_t)NU * HDIM];
__device__ float g_h[(size_t)NE * 64];
__device__ float g_cntE[NE];
__device__ float g_cntU[NU];

// ---------------- f32x2 packed helpers ----------------
__device__ __forceinline__ void fma_x2(unsigned long long& acc, unsigned long long a,
                                       unsigned long long b) {
    asm("fma.rn.f32x2 %0, %1, %2, %0;" : "+l"(acc) : "l"(a), "l"(b));
}
__device__ __forceinline__ void mul_x2(unsigned long long& acc, unsigned long long s) {
    asm("mul.rn.f32x2 %0, %0, %1;" : "+l"(acc) : "l"(s));
}
__device__ __forceinline__ unsigned long long dup_x2(float v) {
    unsigned long long r;
    asm("mov.b64 %0, {%1, %1};" : "=l"(r) : "f"(v));
    return r;
}
__device__ __forceinline__ unsigned long long pack_x2(float lo, float hi) {
    unsigned long long r;
    asm("mov.b64 %0, {%1, %2};" : "=l"(r) : "f"(lo), "f"(hi));
    return r;
}
__device__ __forceinline__ void unpack_x2(unsigned long long v, float& lo, float& hi) {
    asm("mov.b64 {%0, %1}, %2;" : "=f"(lo), "=f"(hi) : "l"(v));
}

// ---------------- fused zero kernel (single launch) ----------------
__global__ void zero_all(float4* accE, float4* accE2, float4* accU,
                         float4* cntE, float4* cntU) {
    const int nE4 = NE * HDIM / 4, nU4 = NU * HDIM / 4;
    const int cE4 = NE / 4, cU4 = NU / 4;
    float4 z = make_float4(0.f, 0.f, 0.f, 0.f);
    int i = blockIdx.x * blockDim.x + threadIdx.x;
    int stride = gridDim.x * blockDim.x;
    for (int k = i; k < nE4; k += stride) { accE[k] = z; accE2[k] = z; }
    for (int k = i; k < nU4; k += stride) accU[k] = z;
    for (int k = i; k < cE4; k += stride) cntE[k] = z;
    for (int k = i; k < cU4; k += stride) cntU[k] = z;
}

// ---------------- edge scatter: one warp per edge, vector RED ----------------
__global__ void scatter_kernel(const int* __restrict__ src, const int* __restrict__ dst,
                               const float* __restrict__ xsrc,
                               float* __restrict__ accum, float* __restrict__ cnt,
                               int nE, int doCnt)
{
    int gt = blockIdx.x * blockDim.x + threadIdx.x;
    int e = gt >> 5, lane = gt & 31;
    if (e >= nE) return;
    int s = __ldg(src + e);
    int d = __ldg(dst + e);
    float4 v = *reinterpret_cast<const float4*>(xsrc + (size_t)s * HDIM + lane * 4);
    float* a = accum + (size_t)d * HDIM + lane * 4;
    asm volatile("red.global.add.v4.f32 [%0], {%1, %2, %3, %4};"
                 :: "l"(a), "f"(v.x), "f"(v.y), "f"(v.z), "f"(v.w) : "memory");
    if (doCnt && lane == 0) atomicAdd(cnt + d, 1.0f);
}

// ---------------- fused combine GEMM: double-buffered, f32x2, float4 loads ------
// out[M,128] = epi( A1[M,K1]*(1/max(cnt,1)) @ W1[128,K1]^T
//                   + (HAS_A2 ? A2[M,128] @ W2[128,128]^T : 0) + bias )
// BM=128, BN=128, BK=32, 256 threads; per thread 8 rows (4 f32x2 pairs) x 8 cols.
template<bool HAS_A2, bool RELU, bool MEAN>
__global__ void __launch_bounds__(256)
gemm_combine(const float* __restrict__ A1, int K1,
             const float* __restrict__ W1,
             const float* __restrict__ A2,
             const float* __restrict__ W2,
             const float* __restrict__ bias,
             const float* __restrict__ cnt,
             float* __restrict__ out, int M)
{
    __shared__ float As[2][32][132];
    __shared__ float Ws[2][32][132];
    int tid = threadIdx.x;
    int ty = tid >> 4, tx = tid & 15;
    int row0 = blockIdx.x * 128;

    const int nt1 = K1 >> 5;                   // tiles in phase 0
    const int total = nt1 + (HAS_A2 ? 4 : 0);  // phase 1 is K=128 -> 4 tiles

    // per-thread load coords: 4 float4 for A tile, 4 for W tile
    // A tile: 128 rows x 8 quads; idx = tid + it*256; r = idx>>3, q = idx&7
    unsigned long long acc[4][8];
#pragma unroll
    for (int p = 0; p < 4; p++)
#pragma unroll
        for (int j = 0; j < 8; j++) acc[p][j] = 0ULL;

    // tile t -> (A,W,K,k0)
    auto ldg_tile = [&](int t, float4 la[4], float4 lw[4]) {
        const float* A; const float* W; int K, k0;
        if (t < nt1) { A = A1; W = W1; K = K1; k0 = t << 5; }
        else         { A = A2; W = W2; K = 128; k0 = (t - nt1) << 5; }
#pragma unroll
        for (int it = 0; it < 4; it++) {
            int idx = tid + it * 256;
            int r = idx >> 3, q = idx & 7;
            int gr = row0 + r;
            la[it] = (gr < M) ? *reinterpret_cast<const float4*>(A + (size_t)gr * K + k0 + q * 4)
                              : make_float4(0.f, 0.f, 0.f, 0.f);
            lw[it] = *reinterpret_cast<const float4*>(W + (size_t)(idx >> 3) * K + k0 + (idx & 7) * 4);
        }
    };
    auto sts_tile = [&](const float4 la[4], const float4 lw[4], int buf) {
#pragma unroll
        for (int it = 0; it < 4; it++) {
            int idx = tid + it * 256;
            int r = idx >> 3, q = idx & 7;
            As[buf][q * 4 + 0][r] = la[it].x;
            As[buf][q * 4 + 1][r] = la[it].y;
            As[buf][q * 4 + 2][r] = la[it].z;
            As[buf][q * 4 + 3][r] = la[it].w;
            Ws[buf][q * 4 + 0][r] = lw[it].x;
            Ws[buf][q * 4 + 1][r] = lw[it].y;
            Ws[buf][q * 4 + 2][r] = lw[it].z;
            Ws[buf][q * 4 + 3][r] = lw[it].w;
        }
    };

    {   // prologue
        float4 la[4], lw[4];
        ldg_tile(0, la, lw);
        sts_tile(la, lw, 0);
    }
    __syncthreads();

    for (int t = 0; t < total; t++) {
        int cur = t & 1;
        float4 la[4], lw[4];
        if (t + 1 < total) ldg_tile(t + 1, la, lw);
#pragma unroll
        for (int kk = 0; kk < 32; kk++) {
            unsigned long long a2[4];
#pragma unroll
            for (int p = 0; p < 4; p++)
                a2[p] = *reinterpret_cast<const unsigned long long*>(&As[cur][kk][ty * 8 + 2 * p]);
            unsigned long long wd[8];
#pragma unroll
            for (int j = 0; j < 8; j++) wd[j] = dup_x2(Ws[cur][kk][tx * 8 + j]);
#pragma unroll
            for (int p = 0; p < 4; p++)
#pragma unroll
                for (int j = 0; j < 8; j++) fma_x2(acc[p][j], a2[p], wd[j]);
        }
        // end of phase 0: fold in 1/cnt (diag scaling commutes with GEMM)
        if (MEAN && t == nt1 - 1) {
#pragma unroll
            for (int p = 0; p < 4; p++) {
                int gr0 = row0 + ty * 8 + 2 * p;
                int gr1 = gr0 + 1;
                float c0 = (gr0 < M) ? cnt[gr0] : 1.f;
                float c1 = (gr1 < M) ? cnt[gr1] : 1.f;
                unsigned long long invp = pack_x2(1.f / fmaxf(c0, 1.f), 1.f / fmaxf(c1, 1.f));
#pragma unroll
                for (int j = 0; j < 8; j++) mul_x2(acc[p][j], invp);
            }
        }
        if (t + 1 < total) sts_tile(la, lw, cur ^ 1);
        __syncthreads();
    }

    float bj[8];
#pragma unroll
    for (int j = 0; j < 8; j++) bj[j] = bias[tx * 8 + j];

#pragma unroll
    for (int p = 0; p < 4; p++) {
        int gr0 = row0 + ty * 8 + 2 * p;
        int gr1 = gr0 + 1;
        float r0[8], r1[8];
#pragma unroll
        for (int j = 0; j < 8; j++) {
            unpack_x2(acc[p][j], r0[j], r1[j]);
            r0[j] += bj[j]; r1[j] += bj[j];
            if (RELU) { r0[j] = fmaxf(r0[j], 0.f); r1[j] = fmaxf(r1[j], 0.f); }
        }
        if (gr0 < M) {
            float4* o = reinterpret_cast<float4*>(out + (size_t)gr0 * 128 + tx * 8);
            o[0] = make_float4(r0[0], r0[1], r0[2], r0[3]);
            o[1] = make_float4(r0[4], r0[5], r0[6], r0[7]);
        }
        if (gr1 < M) {
            float4* o = reinterpret_cast<float4*>(out + (size_t)gr1 * 128 + tx * 8);
            o[0] = make_float4(r1[0], r1[1], r1[2], r1[3]);
            o[1] = make_float4(r1[4], r1[5], r1[6], r1[7]);
        }
    }
}

// ---------------- B-spline bases (uniform grid, grid_size=5, k=3 -> 8 bases) ----
__device__ __forceinline__ void bspline8(float x, float b[8]) {
    const float hstep = 2.0f / 5.0f;
    float g[12];
#pragma unroll
    for (int t = 0; t < 12; t++) g[t] = (float)(t - 3) * hstep - 1.0f;
    float p0[11], p1[10], p2[9];
#pragma unroll
    for (int t = 0; t < 11; t++) p0[t] = (x >= g[t] && x < g[t + 1]) ? 1.0f : 0.0f;
#pragma unroll
    for (int t = 0; t < 10; t++)
        p1[t] = (x - g[t]) * (1.0f / (g[t + 1] - g[t])) * p0[t]
              + (g[t + 2] - x) * (1.0f / (g[t + 2] - g[t + 1])) * p0[t + 1];
#pragma unroll
    for (int t = 0; t < 9; t++)
        p2[t] = (x - g[t]) * (1.0f / (g[t + 2] - g[t])) * p1[t]
              + (g[t + 3] - x) * (1.0f / (g[t + 3] - g[t + 1])) * p1[t + 1];
#pragma unroll
    for (int t = 0; t < 8; t++)
        b[t] = (x - g[t]) * (1.0f / (g[t + 3] - g[t])) * p2[t]
             + (g[t + 4] - x) * (1.0f / (g[t + 4] - g[t + 1])) * p2[t + 1];
}

__device__ __forceinline__ float silu(float x) {
    return x / (1.0f + __expf(-x));
}

// ---------------- KAN layer 1: [M,128] -> [M,64], pipelined spline phase --------
// BM=128 rows, 64 cols, 256 threads (ty: 8 rows = 4 f32x2 pairs; tx: 4 cols)
__global__ void __launch_bounds__(256)
kan1_kernel(const float* __restrict__ x,      // [M,128]
            const float* __restrict__ spline,  // [64,128,8]
            const float* __restrict__ scaler,  // [64,128]
            const float* __restrict__ basew,   // [64,128]
            float* __restrict__ out, int M)    // [M,64]
{
    __shared__ float Bs[2][32][130];   // even stride -> 8B-aligned 64-bit LDS
    __shared__ float Ws[2][32][66];
    int tid = threadIdx.x;
    int ty = tid >> 4, tx = tid & 15;
    int row0 = blockIdx.x * 128;
    unsigned long long acc[4][4];
#pragma unroll
    for (int p = 0; p < 4; p++)
#pragma unroll
        for (int j = 0; j < 4; j++) acc[p][j] = 0ULL;

    // --- spline phase: 32 chunks of 4 input features (32 basis K each), pipelined
    auto fill_chunk = [&](int c, float nb[2][8], float nw[8]) {
        int f0 = c * 4;
#pragma unroll
        for (int it = 0; it < 2; it++) {
            int p = tid + it * 256;
            int feat = p & 3, r = p >> 2;
            int gr = row0 + r;
            float xv = (gr < M) ? x[(size_t)gr * 128 + f0 + feat] : 0.f;
            bspline8(xv, nb[it]);
        }
#pragma unroll
        for (int it = 0; it < 8; it++) {
            int idx = tid + it * 256;
            int kk = idx & 31, col = idx >> 5;
            nw[it] = spline[(size_t)col * 1024 + f0 * 8 + kk] * scaler[col * 128 + f0 + (kk >> 3)];
        }
    };
    auto sts_chunk = [&](const float nb[2][8], const float nw[8], int buf) {
#pragma unroll
        for (int it = 0; it < 2; it++) {
            int p = tid + it * 256;
            int feat = p & 3, r = p >> 2;
#pragma unroll
            for (int t = 0; t < 8; t++) Bs[buf][feat * 8 + t][r] = nb[it][t];
        }
#pragma unroll
        for (int it = 0; it < 8; it++) {
            int idx = tid + it * 256;
            Ws[buf][idx & 31][idx >> 5] = nw[it];
        }
    };

    {
        float nb[2][8], nw[8];
        fill_chunk(0, nb, nw);
        sts_chunk(nb, nw, 0);
    }
    __syncthreads();

    for (int c = 0; c < 32; c++) {
        int cur = c & 1;
        float nb[2][8], nw[8];
        if (c + 1 < 32) fill_chunk(c + 1, nb, nw);
#pragma unroll
        for (int kk = 0; kk < 32; kk++) {
            unsigned long long a2[4];
#pragma unroll
            for (int p = 0; p < 4; p++)
                a2[p] = *reinterpret_cast<const unsigned long long*>(&Bs[cur][kk][ty * 8 + 2 * p]);
            unsigned long long wd[4];
#pragma unroll
            for (int j = 0; j < 4; j++) wd[j] = dup_x2(Ws[cur][kk][tx * 4 + j]);
#pragma unroll
            for (int p = 0; p < 4; p++)
#pragma unroll
                for (int j = 0; j < 4; j++) fma_x2(acc[p][j], a2[p], wd[j]);
        }
        if (c + 1 < 32) sts_chunk(nb, nw, cur ^ 1);
        __syncthreads();
    }

    // --- base phase: silu(x) @ base_w^T, 4 chunks of 32 features, pipelined too
    auto fill_base = [&](int f0, float nb[2], float nw[2]) {
#pragma unroll
        for (int it = 0; it < 2; it++) {
            int p = tid + it * 256;
            int feat = p & 31, r = p >> 5;   // wait: 256*2=512, need 128*32=4096
            (void)feat; (void)r;
            nb[it] = 0.f; nw[it] = 0.f;
        }
    };
    (void)fill_base;
    for (int f0 = 0; f0 < 128; f0 += 32) {
#pragma unroll
        for (int it = 0; it < 16; it++) {
            int p = tid + it * 256;
            int feat = p & 31, r = p >> 5;
            int gr = row0 + r;
            float xv = (gr < M) ? x[(size_t)gr * 128 + f0 + feat] : 0.f;
            Bs[0][feat][r] = silu(xv);
        }
#pragma unroll
        for (int it = 0; it < 8; it++) {
            int idx = tid + it * 256;
            int kk = idx & 31, col = idx >> 5;
            Ws[0][kk][col] = basew[(size_t)col * 128 + f0 + kk];
        }
        __syncthreads();
#pragma unroll
        for (int kk = 0; kk < 32; kk++) {
            unsigned long long a2[4];
#pragma unroll
            for (int p = 0; p < 4; p++)
                a2[p] = *reinterpret_cast<const unsigned long long*>(&Bs[0][kk][ty * 8 + 2 * p]);
            unsigned long long wd[4];
#pragma unroll
            for (int j = 0; j < 4; j++) wd[j] = dup_x2(Ws[0][kk][tx * 4 + j]);
#pragma unroll
            for (int p = 0; p < 4; p++)
#pragma unroll
                for (int j = 0; j < 4; j++) fma_x2(acc[p][j], a2[p], wd[j]);
        }
        __syncthreads();
    }

#pragma unroll
    for (int p = 0; p < 4; p++) {
        int gr0 = row0 + ty * 8 + 2 * p;
        int gr1 = gr0 + 1;
        float r0[4], r1[4];
#pragma unroll
        for (int j = 0; j < 4; j++) unpack_x2(acc[p][j], r0[j], r1[j]);
        if (gr0 < M)
            *reinterpret_cast<float4*>(out + (size_t)gr0 * 64 + tx * 4) =
                make_float4(r0[0], r0[1], r0[2], r0[3]);
        if (gr1 < M)
            *reinterpret_cast<float4*>(out + (size_t)gr1 * 64 + tx * 4) =
                make_float4(r1[0], r1[1], r1[2], r1[3]);
    }
}

// ---------------- KAN layer 2: [M,64] -> [M,2], one thread per row ----------------
__global__ void kan2_kernel(const float* __restrict__ hin,     // [M,64]
                            const float* __restrict__ spline,  // [2,64,8]
                            const float* __restrict__ scaler,  // [2,64]
                            const float* __restrict__ basew,   // [2,64]
                            float* __restrict__ out, int M)    // [M,2]
{
    __shared__ float sh[128][65];
    __shared__ float sw[2][64][8];
    __shared__ float sb[2][64];
    int tid = threadIdx.x;
    int row0 = blockIdx.x * 128;
    for (int idx = tid; idx < 1024; idx += 128) {
        int o = idx >> 9, rem = idx & 511, f = rem >> 3, t = rem & 7;
        sw[o][f][t] = spline[idx] * scaler[o * 64 + f];
    }
    if (tid < 128) sb[tid >> 6][tid & 63] = basew[tid];
    for (int idx = tid; idx < 128 * 64; idx += 128) {
        int r = idx >> 6, f = idx & 63;
        int gr = row0 + r;
        sh[r][f] = (gr < M) ? hin[(size_t)gr * 64 + f] : 0.f;
    }
    __syncthreads();
    int gr = row0 + tid;
    if (gr >= M) return;
    float acc0 = 0.f, acc1 = 0.f;
    for (int f = 0; f < 64; f++) {
        float xv = sh[tid][f];
        float s = silu(xv);
        acc0 += s * sb[0][f];
        acc1 += s * sb[1][f];
        float b[8];
        bspline8(xv, b);
#pragma unroll
        for (int t = 0; t < 8; t++) {
            acc0 += b[t] * sw[0][f][t];
            acc1 += b[t] * sw[1][f][t];
        }
    }
    out[(size_t)gr * 2 + 0] = acc0;
    out[(size_t)gr * 2 + 1] = acc1;
}

// ---------------- launch ----------------
extern "C" void kernel_launch(void* const* d_in, const int* in_sizes, int n_in,
                              void* d_out, int out_size)
{
    const float* x_email    = (const float*)d_in[0];
    const int*   ei_ue      = (const int*)d_in[1];   // [2,E]: row0=src(user), row1=dst(email)
    const int*   ei_eu      = (const int*)d_in[2];   // [2,E]: row0=src(email), row1=dst(user)
    const float* w_email    = (const float*)d_in[3];
    const float* b_email    = (const float*)d_in[4];
    const float* emb_user   = (const float*)d_in[5];
    const float* w_l1_ue_n  = (const float*)d_in[6];
    const float* b_l1_ue    = (const float*)d_in[7];
    const float* w_l1_ue_r  = (const float*)d_in[8];
    const float* w_l1_eu_n  = (const float*)d_in[9];
    const float* b_l1_eu    = (const float*)d_in[10];
    const float* w_l1_eu_r  = (const float*)d_in[11];
    const float* w_l2_ue_n  = (const float*)d_in[12];
    const float* b_l2_ue    = (const float*)d_in[13];
    const float* w_l2_ue_r  = (const float*)d_in[14];
    // 15..17: l2_eu weights (unused by the reference output path)
    const float* kan1_base   = (const float*)d_in[18];
    const float* kan1_spline = (const float*)d_in[19];
    const float* kan1_scaler = (const float*)d_in[20];
    // 21: grid1 (uniform; recomputed in-kernel)
    const float* kan2_base   = (const float*)d_in[22];
    const float* kan2_spline = (const float*)d_in[23];
    const float* kan2_scaler = (const float*)d_in[24];
    // 25: grid2
    float* out = (float*)d_out;

    float *xe, *accE, *accE2, *e1, *accU, *u1, *hbuf, *cntE, *cntU;
    cudaGetSymbolAddress((void**)&xe,    g_xe);
    cudaGetSymbolAddress((void**)&accE,  g_accE);
    cudaGetSymbolAddress((void**)&accE2, g_accE2);
    cudaGetSymbolAddress((void**)&e1,    g_e1);
    cudaGetSymbolAddress((void**)&accU,  g_accU);
    cudaGetSymbolAddress((void**)&u1,    g_u1);
    cudaGetSymbolAddress((void**)&hbuf,  g_h);
    cudaGetSymbolAddress((void**)&cntE,  g_cntE);
    cudaGetSymbolAddress((void**)&cntU,  g_cntU);

    int gE = (NE + 127) / 128;   // 1563
    int gU = (NU + 127) / 128;   // 782
    int gScat = (NEDGE * 32 + 255) / 256;  // 125000

    // 1: zero all accumulators/counts in one launch
    zero_all<<<8192, 256>>>((float4*)accE, (float4*)accE2, (float4*)accU,
                            (float4*)cntE, (float4*)cntU);
    // 2: xe = x_email @ w_email^T + b_email
    gemm_combine<false, false, false><<<gE, 256>>>(x_email, 64, w_email,
                                                   nullptr, nullptr, b_email,
                                                   nullptr, xe, NE);
    // 3: conv1 email aggregate
    scatter_kernel<<<gScat, 256>>>(ei_ue, ei_ue + NEDGE, emb_user, accE, cntE, NEDGE, 1);
    // 4: conv1 email combine
    gemm_combine<true, true, true><<<gE, 256>>>(accE, 128, w_l1_ue_n,
                                                xe, w_l1_ue_r, b_l1_ue,
                                                cntE, e1, NE);
    // 5: conv1 user aggregate
    scatter_kernel<<<gScat, 256>>>(ei_eu, ei_eu + NEDGE, xe, accU, cntU, NEDGE, 1);
    // 6: conv1 user combine
    gemm_combine<true, true, true><<<gU, 256>>>(accU, 128, w_l1_eu_n,
                                                emb_user, w_l1_eu_r, b_l1_eu,
                                                cntU, u1, NU);
    // 7: conv2 email aggregate (separate pre-zeroed accumulator)
    scatter_kernel<<<gScat, 256>>>(ei_ue, ei_ue + NEDGE, u1, accE2, nullptr, NEDGE, 0);
    // 8: conv2 email combine
    gemm_combine<true, true, true><<<gE, 256>>>(accE2, 128, w_l2_ue_n,
                                                e1, w_l2_ue_r, b_l2_ue,
                                                cntE, xe /*= e2*/, NE);
    // 9-10: KAN head
    kan1_kernel<<<gE, 256>>>(xe, kan1_spline, kan1_scaler, kan1_base, hbuf, NE);
    kan2_kernel<<<gE, 128>>>(hbuf, kan2_spline, kan2_scaler, kan2_base, out, NE);
}

// round 5
// speedup vs baseline: 1.7747x; 1.1992x over previous
#include <cuda_runtime.h>
#include <math.h>
#include <stdint.h>

#define NE 200000
#define NU 100000
#define NEDGE 1000000
#define HDIM 128

// ---------------- scratch (static device arrays; no allocation) ----------------
__device__ float g_xe[(size_t)NE * HDIM];     // xe, later reused for e2
__device__ float g_accE[(size_t)NE * HDIM];   // accum for conv1-email
__device__ float g_accE2[(size_t)NE * HDIM];  // accum for conv2-email
__device__ float g_e1[(size_t)NE * HDIM];
__device__ float g_accU[(size_t)NU * HDIM];
__device__ float g_u1[(size_t)NU * HDIM];
__device__ float g_h[(size_t)NE * 64];
__device__ float g_cntE[NE];
__device__ float g_cntU[NU];
// transposed weights: [K][128] layouts
__device__ float g_wTe[64 * 128];
__device__ float g_wT1n[128 * 128];
__device__ float g_wT1r[128 * 128];
__device__ float g_wT2n[128 * 128];
__device__ float g_wT2r[128 * 128];
__device__ float g_wT3n[128 * 128];
__device__ float g_wT3r[128 * 128];

// ---------------- f32x2 packed helpers ----------------
__device__ __forceinline__ void fma_x2(unsigned long long& acc, unsigned long long a,
                                       unsigned long long b) {
    asm("fma.rn.f32x2 %0, %1, %2, %0;" : "+l"(acc) : "l"(a), "l"(b));
}
__device__ __forceinline__ void mul_x2(unsigned long long& acc, unsigned long long s) {
    asm("mul.rn.f32x2 %0, %0, %1;" : "+l"(acc) : "l"(s));
}
__device__ __forceinline__ unsigned long long dup_x2(float v) {
    unsigned long long r;
    asm("mov.b64 %0, {%1, %1};" : "=l"(r) : "f"(v));
    return r;
}
__device__ __forceinline__ unsigned long long pack_x2(float lo, float hi) {
    unsigned long long r;
    asm("mov.b64 %0, {%1, %2};" : "=l"(r) : "f"(lo), "f"(hi));
    return r;
}
__device__ __forceinline__ void unpack_x2(unsigned long long v, float& lo, float& hi) {
    asm("mov.b64 {%0, %1}, %2;" : "=f"(lo), "=f"(hi) : "l"(v));
}
__device__ __forceinline__ uint32_t smem_u32(const void* p) {
    return (uint32_t)__cvta_generic_to_shared(p);
}
__device__ __forceinline__ void cp_async16(uint32_t dst, const void* src) {
    asm volatile("cp.async.ca.shared.global [%0], [%1], 16;" :: "r"(dst), "l"(src));
}
__device__ __forceinline__ void cp_commit() { asm volatile("cp.async.commit_group;"); }
__device__ __forceinline__ void cp_wait_all() {
    asm volatile("cp.async.wait_group 0;" ::: "memory");
}

// ---------------- weight pre-transpose (runs once per launch, tiny) ----------------
__global__ void transpose_weights(const float* we, const float* w1n, const float* w1r,
                                  const float* w2n, const float* w2r,
                                  const float* w3n, const float* w3r)
{
    int i = blockIdx.x * blockDim.x + threadIdx.x;
    if (i < 64 * 128) {             // w_email [128][64] -> [64][128]
        int k = i >> 7, c = i & 127;
        g_wTe[i] = we[c * 64 + k];
        return;
    }
    int j = i - 64 * 128;
    int m = j >> 14;                // which 128x128 matrix
    int r = j & 16383;
    int k = r >> 7, c = r & 127;
    const float* src;
    float* dst;
    switch (m) {
        case 0: src = w1n; dst = g_wT1n; break;
        case 1: src = w1r; dst = g_wT1r; break;
        case 2: src = w2n; dst = g_wT2n; break;
        case 3: src = w2r; dst = g_wT2r; break;
        case 4: src = w3n; dst = g_wT3n; break;
        default: src = w3r; dst = g_wT3r; break;
    }
    dst[r] = src[c * 128 + k];
}

// ---------------- fused zero kernel (single launch) ----------------
__global__ void zero_all(float4* accE, float4* accE2, float4* accU,
                         float4* cntE, float4* cntU) {
    const int nE4 = NE * HDIM / 4, nU4 = NU * HDIM / 4;
    const int cE4 = NE / 4, cU4 = NU / 4;
    float4 z = make_float4(0.f, 0.f, 0.f, 0.f);
    int i = blockIdx.x * blockDim.x + threadIdx.x;
    int stride = gridDim.x * blockDim.x;
    for (int k = i; k < nE4; k += stride) { accE[k] = z; accE2[k] = z; }
    for (int k = i; k < nU4; k += stride) accU[k] = z;
    for (int k = i; k < cE4; k += stride) cntE[k] = z;
    for (int k = i; k < cU4; k += stride) cntU[k] = z;
}

// ---------------- edge scatter: one warp per 8 edges (MLP=8), vector RED --------
__global__ void scatter_kernel(const int* __restrict__ src, const int* __restrict__ dst,
                               const float* __restrict__ xsrc,
                               float* __restrict__ accum, float* __restrict__ cnt,
                               int doCnt)
{
    int warp = (blockIdx.x * blockDim.x + threadIdx.x) >> 5;
    int lane = threadIdx.x & 31;
    int e0 = warp * 8;
    if (e0 >= NEDGE) return;
    int4 sa = *reinterpret_cast<const int4*>(src + e0);
    int4 sb = *reinterpret_cast<const int4*>(src + e0 + 4);
    int4 da = *reinterpret_cast<const int4*>(dst + e0);
    int4 db = *reinterpret_cast<const int4*>(dst + e0 + 4);
    int s[8] = {sa.x, sa.y, sa.z, sa.w, sb.x, sb.y, sb.z, sb.w};
    int d[8] = {da.x, da.y, da.z, da.w, db.x, db.y, db.z, db.w};
    float4 v[8];
#pragma unroll
    for (int i = 0; i < 8; i++)
        v[i] = *reinterpret_cast<const float4*>(xsrc + (size_t)s[i] * HDIM + lane * 4);
#pragma unroll
    for (int i = 0; i < 8; i++) {
        float* a = accum + (size_t)d[i] * HDIM + lane * 4;
        asm volatile("red.global.add.v4.f32 [%0], {%1, %2, %3, %4};"
                     :: "l"(a), "f"(v[i].x), "f"(v[i].y), "f"(v[i].z), "f"(v[i].w) : "memory");
    }
    if (doCnt && lane == 0) {
#pragma unroll
        for (int i = 0; i < 8; i++) {
            float one = 1.0f;
            asm volatile("red.global.add.f32 [%0], %1;" :: "l"(cnt + d[i]), "f"(one) : "memory");
        }
    }
}

// ---------------- fused combine GEMM ----------------
// out[M,128] = epi( A1[M,K1]*(1/max(cnt,1)) @ W1 + (HAS_A2 ? A2[M,128] @ W2 : 0) + bias )
// W given pre-transposed [K][128]. BM=128, BN=128, BK=32, 256 threads.
// Thread (ty,tx): rows ty*8..+7 (4 f32x2 pairs), cols {tx + 16j, j=0..7} (conflict-free).
template<bool HAS_A2, bool RELU, bool MEAN>
__global__ void __launch_bounds__(256, 2)
gemm_combine(const float* __restrict__ A1, int K1,
             const float* __restrict__ W1T,
             const float* __restrict__ A2,
             const float* __restrict__ W2T,
             const float* __restrict__ bias,
             const float* __restrict__ cnt,
             float* __restrict__ out, int M)
{
    __shared__ __align__(16) float As[2][32][130];  // [kk][r], even pitch for LDS.64
    __shared__ __align__(16) float Ws[2][32][132];  // [kk][c], 132*4=528B, 16B-mult
    int tid = threadIdx.x;
    int ty = tid >> 4, tx = tid & 15;
    int row0 = blockIdx.x * 128;

    const int nt1 = K1 >> 5;
    const int total = nt1 + (HAS_A2 ? 4 : 0);

    unsigned long long acc[4][8];
#pragma unroll
    for (int p = 0; p < 4; p++)
#pragma unroll
        for (int j = 0; j < 8; j++) acc[p][j] = 0ULL;

    auto cp_w = [&](int t, int buf) {
        const float* WT = (t < nt1) ? W1T : W2T;
        int k0 = (t < nt1) ? (t << 5) : ((t - nt1) << 5);
#pragma unroll
        for (int it = 0; it < 4; it++) {
            int idx = tid + it * 256;
            int kk = idx >> 5, c4 = idx & 31;
            cp_async16(smem_u32(&Ws[buf][kk][c4 * 4]),
                       WT + (size_t)(k0 + kk) * 128 + c4 * 4);
        }
        cp_commit();
    };
    auto ldg_a = [&](int t, float4 la[4]) {
        const float* A; int K, k0;
        if (t < nt1) { A = A1; K = K1; k0 = t << 5; }
        else         { A = A2; K = 128; k0 = (t - nt1) << 5; }
#pragma unroll
        for (int it = 0; it < 4; it++) {
            int idx = tid + it * 256;
            int r = idx >> 3, q = idx & 7;
            int gr = row0 + r;
            la[it] = (gr < M) ? *reinterpret_cast<const float4*>(A + (size_t)gr * K + k0 + q * 4)
                              : make_float4(0.f, 0.f, 0.f, 0.f);
        }
    };
    auto sts_a = [&](const float4 la[4], int buf) {
#pragma unroll
        for (int it = 0; it < 4; it++) {
            int idx = tid + it * 256;
            int r = idx >> 3, q = idx & 7;
            As[buf][q * 4 + 0][r] = la[it].x;
            As[buf][q * 4 + 1][r] = la[it].y;
            As[buf][q * 4 + 2][r] = la[it].z;
            As[buf][q * 4 + 3][r] = la[it].w;
        }
    };

    {   // prologue
        float4 la[4];
        ldg_a(0, la);
        cp_w(0, 0);
        sts_a(la, 0);
        cp_wait_all();
    }
    __syncthreads();

    for (int t = 0; t < total; t++) {
        int cur = t & 1;
        float4 la[4];
        if (t + 1 < total) { ldg_a(t + 1, la); cp_w(t + 1, cur ^ 1); }
#pragma unroll
        for (int kk = 0; kk < 32; kk++) {
            unsigned long long a2[4];
#pragma unroll
            for (int p = 0; p < 4; p++)
                a2[p] = *reinterpret_cast<const unsigned long long*>(&As[cur][kk][ty * 8 + 2 * p]);
            unsigned long long wd[8];
#pragma unroll
            for (int j = 0; j < 8; j++) wd[j] = dup_x2(Ws[cur][kk][tx + 16 * j]);
#pragma unroll
            for (int p = 0; p < 4; p++)
#pragma unroll
                for (int j = 0; j < 8; j++) fma_x2(acc[p][j], a2[p], wd[j]);
        }
        if (MEAN && t == nt1 - 1) {   // fold 1/cnt between phases
#pragma unroll
            for (int p = 0; p < 4; p++) {
                int gr0 = row0 + ty * 8 + 2 * p;
                int gr1 = gr0 + 1;
                float c0 = (gr0 < M) ? cnt[gr0] : 1.f;
                float c1 = (gr1 < M) ? cnt[gr1] : 1.f;
                unsigned long long invp = pack_x2(1.f / fmaxf(c0, 1.f), 1.f / fmaxf(c1, 1.f));
#pragma unroll
                for (int j = 0; j < 8; j++) mul_x2(acc[p][j], invp);
            }
        }
        if (t + 1 < total) { sts_a(la, cur ^ 1); cp_wait_all(); }
        __syncthreads();
    }

    float bj[8];
#pragma unroll
    for (int j = 0; j < 8; j++) bj[j] = bias[tx + 16 * j];

#pragma unroll
    for (int p = 0; p < 4; p++) {
        int gr0 = row0 + ty * 8 + 2 * p;
        int gr1 = gr0 + 1;
        float r0[8], r1[8];
#pragma unroll
        for (int j = 0; j < 8; j++) {
            unpack_x2(acc[p][j], r0[j], r1[j]);
            r0[j] += bj[j]; r1[j] += bj[j];
            if (RELU) { r0[j] = fmaxf(r0[j], 0.f); r1[j] = fmaxf(r1[j], 0.f); }
        }
        if (gr0 < M) {
#pragma unroll
            for (int j = 0; j < 8; j++) out[(size_t)gr0 * 128 + tx + 16 * j] = r0[j];
        }
        if (gr1 < M) {
#pragma unroll
            for (int j = 0; j < 8; j++) out[(size_t)gr1 * 128 + tx + 16 * j] = r1[j];
        }
    }
}

// ---------------- B-spline bases (uniform grid, grid_size=5, k=3 -> 8 bases) ----
__device__ __forceinline__ void bspline8(float x, float b[8]) {
    const float hstep = 2.0f / 5.0f;
    float g[12];
#pragma unroll
    for (int t = 0; t < 12; t++) g[t] = (float)(t - 3) * hstep - 1.0f;
    float p0[11], p1[10], p2[9];
#pragma unroll
    for (int t = 0; t < 11; t++) p0[t] = (x >= g[t] && x < g[t + 1]) ? 1.0f : 0.0f;
#pragma unroll
    for (int t = 0; t < 10; t++)
        p1[t] = (x - g[t]) * (1.0f / (g[t + 1] - g[t])) * p0[t]
              + (g[t + 2] - x) * (1.0f / (g[t + 2] - g[t + 1])) * p0[t + 1];
#pragma unroll
    for (int t = 0; t < 9; t++)
        p2[t] = (x - g[t]) * (1.0f / (g[t + 2] - g[t])) * p1[t]
              + (g[t + 3] - x) * (1.0f / (g[t + 3] - g[t + 1])) * p1[t + 1];
#pragma unroll
    for (int t = 0; t < 8; t++)
        b[t] = (x - g[t]) * (1.0f / (g[t + 3] - g[t])) * p2[t]
             + (g[t + 4] - x) * (1.0f / (g[t + 4] - g[t + 1])) * p2[t + 1];
}

__device__ __forceinline__ float silu(float x) {
    return x / (1.0f + __expf(-x));
}

// ---------------- KAN layer 1: [M,128] -> [M,64], pipelined spline phase --------
// Thread (ty,tx): rows ty*8..+7 (4 f32x2 pairs), cols {tx + 16j, j=0..3}.
__global__ void __launch_bounds__(256)
kan1_kernel(const float* __restrict__ x,      // [M,128]
            const float* __restrict__ spline,  // [64,128,8]
            const float* __restrict__ scaler,  // [64,128]
            const float* __restrict__ basew,   // [64,128]
            float* __restrict__ out, int M)    // [M,64]
{
    __shared__ __align__(16) float Bs[2][32][130];
    __shared__ __align__(16) float Ws[2][32][66];
    int tid = threadIdx.x;
    int ty = tid >> 4, tx = tid & 15;
    int row0 = blockIdx.x * 128;
    unsigned long long acc[4][4];
#pragma unroll
    for (int p = 0; p < 4; p++)
#pragma unroll
        for (int j = 0; j < 4; j++) acc[p][j] = 0ULL;

    // --- spline phase: 32 chunks of 4 input features (32 basis K each), pipelined
    auto fill_chunk = [&](int c, float nb[2][8], float nw[8]) {
        int f0 = c * 4;
#pragma unroll
        for (int it = 0; it < 2; it++) {
            int p = tid + it * 256;
            int feat = p & 3, r = p >> 2;
            int gr = row0 + r;
            float xv = (gr < M) ? x[(size_t)gr * 128 + f0 + feat] : 0.f;
            bspline8(xv, nb[it]);
        }
#pragma unroll
        for (int it = 0; it < 8; it++) {
            int idx = tid + it * 256;
            int kk = idx & 31, col = idx >> 5;
            nw[it] = spline[(size_t)col * 1024 + f0 * 8 + kk] * scaler[col * 128 + f0 + (kk >> 3)];
        }
    };
    auto sts_chunk = [&](const float nb[2][8], const float nw[8], int buf) {
#pragma unroll
        for (int it = 0; it < 2; it++) {
            int p = tid + it * 256;
            int feat = p & 3, r = p >> 2;
#pragma unroll
            for (int t = 0; t < 8; t++) Bs[buf][feat * 8 + t][r] = nb[it][t];
        }
#pragma unroll
        for (int it = 0; it < 8; it++) {
            int idx = tid + it * 256;
            Ws[buf][idx & 31][idx >> 5] = nw[it];
        }
    };

    {
        float nb[2][8], nw[8];
        fill_chunk(0, nb, nw);
        sts_chunk(nb, nw, 0);
    }
    __syncthreads();

    for (int c = 0; c < 32; c++) {
        int cur = c & 1;
        float nb[2][8], nw[8];
        if (c + 1 < 32) fill_chunk(c + 1, nb, nw);
#pragma unroll
        for (int kk = 0; kk < 32; kk++) {
            unsigned long long a2[4];
#pragma unroll
            for (int p = 0; p < 4; p++)
                a2[p] = *reinterpret_cast<const unsigned long long*>(&Bs[cur][kk][ty * 8 + 2 * p]);
            unsigned long long wd[4];
#pragma unroll
            for (int j = 0; j < 4; j++) wd[j] = dup_x2(Ws[cur][kk][tx + 16 * j]);
#pragma unroll
            for (int p = 0; p < 4; p++)
#pragma unroll
                for (int j = 0; j < 4; j++) fma_x2(acc[p][j], a2[p], wd[j]);
        }
        if (c + 1 < 32) sts_chunk(nb, nw, cur ^ 1);
        __syncthreads();
    }

    // --- base phase: silu(x) @ base_w^T, 4 chunks of 32 features
    for (int f0 = 0; f0 < 128; f0 += 32) {
#pragma unroll
        for (int it = 0; it < 16; it++) {
            int p = tid + it * 256;
            int feat = p & 31, r = p >> 5;
            int gr = row0 + r;
            float xv = (gr < M) ? x[(size_t)gr * 128 + f0 + feat] : 0.f;
            Bs[0][feat][r] = silu(xv);
        }
#pragma unroll
        for (int it = 0; it < 8; it++) {
            int idx = tid + it * 256;
            int kk = idx & 31, col = idx >> 5;
            Ws[0][kk][col] = basew[(size_t)col * 128 + f0 + kk];
        }
        __syncthreads();
#pragma unroll
        for (int kk = 0; kk < 32; kk++) {
            unsigned long long a2[4];
#pragma unroll
            for (int p = 0; p < 4; p++)
                a2[p] = *reinterpret_cast<const unsigned long long*>(&Bs[0][kk][ty * 8 + 2 * p]);
            unsigned long long wd[4];
#pragma unroll
            for (int j = 0; j < 4; j++) wd[j] = dup_x2(Ws[0][kk][tx + 16 * j]);
#pragma unroll
            for (int p = 0; p < 4; p++)
#pragma unroll
                for (int j = 0; j < 4; j++) fma_x2(acc[p][j], a2[p], wd[j]);
        }
        __syncthreads();
    }

#pragma unroll
    for (int p = 0; p < 4; p++) {
        int gr0 = row0 + ty * 8 + 2 * p;
        int gr1 = gr0 + 1;
        float r0[4], r1[4];
#pragma unroll
        for (int j = 0; j < 4; j++) unpack_x2(acc[p][j], r0[j], r1[j]);
        if (gr0 < M) {
#pragma unroll
            for (int j = 0; j < 4; j++) out[(size_t)gr0 * 64 + tx + 16 * j] = r0[j];
        }
        if (gr1 < M) {
#pragma unroll
            for (int j = 0; j < 4; j++) out[(size_t)gr1 * 64 + tx + 16 * j] = r1[j];
        }
    }
}

// ---------------- KAN layer 2: [M,64] -> [M,2], one thread per row ----------------
__global__ void kan2_kernel(const float* __restrict__ hin,     // [M,64]
                            const float* __restrict__ spline,  // [2,64,8]
                            const float* __restrict__ scaler,  // [2,64]
                            const float* __restrict__ basew,   // [2,64]
                            float* __restrict__ out, int M)    // [M,2]
{
    __shared__ float sh[128][65];
    __shared__ float sw[2][64][8];
    __shared__ float sb[2][64];
    int tid = threadIdx.x;
    int row0 = blockIdx.x * 128;
    for (int idx = tid; idx < 1024; idx += 128) {
        int o = idx >> 9, rem = idx & 511, f = rem >> 3, t = rem & 7;
        sw[o][f][t] = spline[idx] * scaler[o * 64 + f];
    }
    if (tid < 128) sb[tid >> 6][tid & 63] = basew[tid];
    for (int idx = tid; idx < 128 * 64; idx += 128) {
        int r = idx >> 6, f = idx & 63;
        int gr = row0 + r;
        sh[r][f] = (gr < M) ? hin[(size_t)gr * 64 + f] : 0.f;
    }
    __syncthreads();
    int gr = row0 + tid;
    if (gr >= M) return;
    float acc0 = 0.f, acc1 = 0.f;
    for (int f = 0; f < 64; f++) {
        float xv = sh[tid][f];
        float s = silu(xv);
        acc0 += s * sb[0][f];
        acc1 += s * sb[1][f];
        float b[8];
        bspline8(xv, b);
#pragma unroll
        for (int t = 0; t < 8; t++) {
            acc0 += b[t] * sw[0][f][t];
            acc1 += b[t] * sw[1][f][t];
        }
    }
    out[(size_t)gr * 2 + 0] = acc0;
    out[(size_t)gr * 2 + 1] = acc1;
}

// ---------------- launch ----------------
extern "C" void kernel_launch(void* const* d_in, const int* in_sizes, int n_in,
                              void* d_out, int out_size)
{
    const float* x_email    = (const float*)d_in[0];
    const int*   ei_ue      = (const int*)d_in[1];
    const int*   ei_eu      = (const int*)d_in[2];
    const float* w_email    = (const float*)d_in[3];
    const float* b_email    = (const float*)d_in[4];
    const float* emb_user   = (const float*)d_in[5];
    const float* w_l1_ue_n  = (const float*)d_in[6];
    const float* b_l1_ue    = (const float*)d_in[7];
    const float* w_l1_ue_r  = (const float*)d_in[8];
    const float* w_l1_eu_n  = (const float*)d_in[9];
    const float* b_l1_eu    = (const float*)d_in[10];
    const float* w_l1_eu_r  = (const float*)d_in[11];
    const float* w_l2_ue_n  = (const float*)d_in[12];
    const float* b_l2_ue    = (const float*)d_in[13];
    const float* w_l2_ue_r  = (const float*)d_in[14];
    const float* kan1_base   = (const float*)d_in[18];
    const float* kan1_spline = (const float*)d_in[19];
    const float* kan1_scaler = (const float*)d_in[20];
    const float* kan2_base   = (const float*)d_in[22];
    const float* kan2_spline = (const float*)d_in[23];
    const float* kan2_scaler = (const float*)d_in[24];
    float* out = (float*)d_out;

    float *xe, *accE, *accE2, *e1, *accU, *u1, *hbuf, *cntE, *cntU;
    cudaGetSymbolAddress((void**)&xe,    g_xe);
    cudaGetSymbolAddress((void**)&accE,  g_accE);
    cudaGetSymbolAddress((void**)&accE2, g_accE2);
    cudaGetSymbolAddress((void**)&e1,    g_e1);
    cudaGetSymbolAddress((void**)&accU,  g_accU);
    cudaGetSymbolAddress((void**)&u1,    g_u1);
    cudaGetSymbolAddress((void**)&hbuf,  g_h);
    cudaGetSymbolAddress((void**)&cntE,  g_cntE);
    cudaGetSymbolAddress((void**)&cntU,  g_cntU);
    float *wTe, *wT1n, *wT1r, *wT2n, *wT2r, *wT3n, *wT3r;
    cudaGetSymbolAddress((void**)&wTe,  g_wTe);
    cudaGetSymbolAddress((void**)&wT1n, g_wT1n);
    cudaGetSymbolAddress((void**)&wT1r, g_wT1r);
    cudaGetSymbolAddress((void**)&wT2n, g_wT2n);
    cudaGetSymbolAddress((void**)&wT2r, g_wT2r);
    cudaGetSymbolAddress((void**)&wT3n, g_wT3n);
    cudaGetSymbolAddress((void**)&wT3r, g_wT3r);

    int gE = (NE + 127) / 128;   // 1563
    int gU = (NU + 127) / 128;   // 782
    int gScat = (NEDGE / 8 * 32 + 255) / 256;  // 15625

    // 0: weight transpose + zero accumulators
    transpose_weights<<<(64*128 + 6*128*128 + 255)/256, 256>>>(
        w_email, w_l1_ue_n, w_l1_ue_r, w_l1_eu_n, w_l1_eu_r, w_l2_ue_n, w_l2_ue_r);
    zero_all<<<8192, 256>>>((float4*)accE, (float4*)accE2, (float4*)accU,
                            (float4*)cntE, (float4*)cntU);
    // 1: xe = x_email @ w_email^T + b_email
    gemm_combine<false, false, false><<<gE, 256>>>(x_email, 64, wTe,
                                                   nullptr, nullptr, b_email,
                                                   nullptr, xe, NE);
    // 2: conv1 email aggregate
    scatter_kernel<<<gScat, 256>>>(ei_ue, ei_ue + NEDGE, emb_user, accE, cntE, 1);
    // 3: conv1 email combine
    gemm_combine<true, true, true><<<gE, 256>>>(accE, 128, wT1n,
                                                xe, wT1r, b_l1_ue,
                                                cntE, e1, NE);
    // 4: conv1 user aggregate
    scatter_kernel<<<gScat, 256>>>(ei_eu, ei_eu + NEDGE, xe, accU, cntU, 1);
    // 5: conv1 user combine
    gemm_combine<true, true, true><<<gU, 256>>>(accU, 128, wT2n,
                                                emb_user, wT2r, b_l1_eu,
                                                cntU, u1, NU);
    // 6: conv2 email aggregate (separate pre-zeroed accumulator)
    scatter_kernel<<<gScat, 256>>>(ei_ue, ei_ue + NEDGE, u1, accE2, nullptr, 0);
    // 7: conv2 email combine
    gemm_combine<true, true, true><<<gE, 256>>>(accE2, 128, wT3n,
                                                e1, wT3r, b_l2_ue,
                                                cntE, xe /*= e2*/, NE);
    // 8-9: KAN head
    kan1_kernel<<<gE, 256>>>(xe, kan1_spline, kan1_scaler, kan1_base, hbuf, NE);
    kan2_kernel<<<gE, 128>>>(hbuf, kan2_spline, kan2_scaler, kan2_base, out, NE);
}